// round 3
// baseline (speedup 1.0000x reference)
#include <cuda_runtime.h>
#include <cstdint>

// ---------------- problem constants ----------------
#define M_TOTAL 8192
#define N_TOTAL 4096
#define K_TOTAL 4096

// ---------------- GEMM tiling ----------------
#define BM 128
#define BN 256
#define BK 32
#define SST 36                      // smem row stride in floats (144B, 16B-aligned)
#define A_STAGE (BM * SST)          // floats
#define B_STAGE (BN * SST)
#define SMEM_FLOATS (2 * (A_STAGE + B_STAGE))
#define SMEM_BYTES  (SMEM_FLOATS * 4)   // 110592

// Scratch: TF32(RNA)-rounded, fragment-permuted copies.
// Within each 32-k block, value k is stored at p = (k%4)*8 + k/4.
__device__ float g_A[(size_t)M_TOTAL * K_TOTAL];   // 134 MB
__device__ float g_WB[(size_t)N_TOTAL * K_TOTAL];  // 67 MB

__device__ __forceinline__ float tf32_rna(float x) {
    unsigned u;
    asm("cvt.rna.tf32.f32 %0, %1;" : "=r"(u) : "f"(x));
    return __uint_as_float(u);
}

__device__ __forceinline__ float comp(const float4& v, int i) {
    return i == 0 ? v.x : (i == 1 ? v.y : (i == 2 ? v.z : v.w));
}

// ---------------- prep kernels: round + permute ----------------
// One thread per 32-float k-block. out[q][u] = in_chunk[4*(q&1)+u].comp[q>>1]
__global__ void prep_a_kernel(const float4* __restrict__ in, float4* __restrict__ outp,
                              int nblocks) {
    int b = blockIdx.x * blockDim.x + threadIdx.x;
    if (b >= nblocks) return;
    float4 v[8];
    #pragma unroll
    for (int c = 0; c < 8; c++) v[c] = in[(size_t)b * 8 + c];
    #pragma unroll
    for (int q = 0; q < 8; q++) {
        int cb = 4 * (q & 1), s = q >> 1;
        float4 r;
        r.x = tf32_rna(comp(v[cb + 0], s));
        r.y = tf32_rna(comp(v[cb + 1], s));
        r.z = tf32_rna(comp(v[cb + 2], s));
        r.w = tf32_rna(comp(v[cb + 3], s));
        outp[(size_t)b * 8 + q] = r;
    }
}

__global__ void prep_w_kernel(const float4* __restrict__ w, const float4* __restrict__ m,
                              float4* __restrict__ outp, int nblocks) {
    int b = blockIdx.x * blockDim.x + threadIdx.x;
    if (b >= nblocks) return;
    float4 v[8];
    #pragma unroll
    for (int c = 0; c < 8; c++) {
        float4 a = w[(size_t)b * 8 + c], k = m[(size_t)b * 8 + c];
        v[c].x = a.x * k.x; v[c].y = a.y * k.y; v[c].z = a.z * k.z; v[c].w = a.w * k.w;
    }
    #pragma unroll
    for (int q = 0; q < 8; q++) {
        int cb = 4 * (q & 1), s = q >> 1;
        float4 r;
        r.x = tf32_rna(comp(v[cb + 0], s));
        r.y = tf32_rna(comp(v[cb + 1], s));
        r.z = tf32_rna(comp(v[cb + 2], s));
        r.w = tf32_rna(comp(v[cb + 3], s));
        outp[(size_t)b * 8 + q] = r;
    }
}

// ---------------- GEMM ----------------
__device__ __forceinline__ void cp_async16(void* dst, const void* src) {
    unsigned sdst = (unsigned)__cvta_generic_to_shared(dst);
    asm volatile("cp.async.cg.shared.global [%0], [%1], 16;" :: "r"(sdst), "l"(src));
}

__device__ __forceinline__ void mma_tf32(float* c,
                                         unsigned a0, unsigned a1, unsigned a2, unsigned a3,
                                         unsigned b0, unsigned b1) {
    asm volatile(
        "mma.sync.aligned.m16n8k8.row.col.f32.tf32.tf32.f32 "
        "{%0,%1,%2,%3}, {%4,%5,%6,%7}, {%8,%9}, {%0,%1,%2,%3};"
        : "+f"(c[0]), "+f"(c[1]), "+f"(c[2]), "+f"(c[3])
        : "r"(a0), "r"(a1), "r"(a2), "r"(a3), "r"(b0), "r"(b1));
}

#define FU(x) __float_as_uint(x)

__global__ __launch_bounds__(256, 1)
void gemm_tf32_kernel(float* __restrict__ out, const float* __restrict__ bias) {
    extern __shared__ float smem[];
    float* As = smem;                  // [2][BM][SST]
    float* Bs = smem + 2 * A_STAGE;    // [2][BN][SST]

    const int tid  = threadIdx.x;
    const int wid  = tid >> 5;
    const int lane = tid & 31;
    const int g    = lane >> 2;        // 0..7
    const int t4   = lane & 3;         // 0..3

    const int warp_m = (wid & 1) * 64;       // 0,64
    const int warp_n = (wid >> 1) * 64;      // 0,64,128,192

    const int bm = blockIdx.y * BM;
    const int bn = blockIdx.x * BN;

    const float* Abase = g_A  + (size_t)bm * K_TOTAL;
    const float* Bbase = g_WB + (size_t)bn * K_TOTAL;

    float acc[4][8][4];
    #pragma unroll
    for (int i = 0; i < 4; i++)
        #pragma unroll
        for (int j = 0; j < 8; j++)
            #pragma unroll
            for (int r = 0; r < 4; r++) acc[i][j][r] = 0.0f;

    // Loader: A 1024 chunks + B 2048 chunks of 16B per stage; 12 per thread.
    auto load_tile = [&](int kt, int buf) {
        const int k0 = kt * BK;
        #pragma unroll
        for (int it = 0; it < 4; it++) {          // A
            int idx = tid + it * 256;
            int row = idx >> 3, ch = idx & 7;
            cp_async16(&As[buf * A_STAGE + row * SST + ch * 4],
                       Abase + (size_t)row * K_TOTAL + k0 + ch * 4);
        }
        #pragma unroll
        for (int it = 0; it < 8; it++) {          // B
            int idx = tid + it * 256;
            int row = idx >> 3, ch = idx & 7;
            cp_async16(&Bs[buf * B_STAGE + row * SST + ch * 4],
                       Bbase + (size_t)row * K_TOTAL + k0 + ch * 4);
        }
        asm volatile("cp.async.commit_group;");
    };

    load_tile(0, 0);

    const int KT = K_TOTAL / BK;  // 128
    for (int kt = 0; kt < KT; ++kt) {
        asm volatile("cp.async.wait_group 0;");
        __syncthreads();
        const int buf = kt & 1;
        if (kt + 1 < KT) load_tile(kt + 1, buf ^ 1);

        const float* Ab = &As[buf * A_STAGE];
        const float* Bb = &Bs[buf * B_STAGE];

        #pragma unroll
        for (int ksp = 0; ksp < 2; ++ksp) {
            const int c = t4 * 8 + ksp * 4;       // permuted col, float4-aligned
            float4 aF[4][2];
            float4 bF[8];
            #pragma unroll
            for (int i = 0; i < 4; i++) {
                aF[i][0] = *reinterpret_cast<const float4*>(Ab + (warp_m + i * 16 + g) * SST + c);
                aF[i][1] = *reinterpret_cast<const float4*>(Ab + (warp_m + i * 16 + g + 8) * SST + c);
            }
            #pragma unroll
            for (int j = 0; j < 8; j++)
                bF[j] = *reinterpret_cast<const float4*>(Bb + (warp_n + j * 8 + g) * SST + c);

            #pragma unroll
            for (int i = 0; i < 4; i++) {
                #pragma unroll
                for (int j = 0; j < 8; j++) {
                    // ks = 2*ksp   : components .x (k=t4), .y (k=t4+4)
                    mma_tf32(acc[i][j],
                             FU(aF[i][0].x), FU(aF[i][1].x), FU(aF[i][0].y), FU(aF[i][1].y),
                             FU(bF[j].x), FU(bF[j].y));
                    // ks = 2*ksp+1 : components .z, .w
                    mma_tf32(acc[i][j],
                             FU(aF[i][0].z), FU(aF[i][1].z), FU(aF[i][0].w), FU(aF[i][1].w),
                             FU(bF[j].z), FU(bF[j].w));
                }
            }
        }
    }

    // Epilogue: c0,c1 @ (g, t4*2 / +1); c2,c3 @ row g+8. float2 STG, bias fused.
    const int row0 = bm + warp_m;
    const int col0 = bn + warp_n;
    #pragma unroll
    for (int i = 0; i < 4; i++) {
        #pragma unroll
        for (int j = 0; j < 8; j++) {
            int r = row0 + i * 16 + g;
            int c = col0 + j * 8 + t4 * 2;
            float b0 = __ldg(bias + c), b1 = __ldg(bias + c + 1);
            float2 v0 = make_float2(acc[i][j][0] + b0, acc[i][j][1] + b1);
            float2 v1 = make_float2(acc[i][j][2] + b0, acc[i][j][3] + b1);
            *reinterpret_cast<float2*>(out + (size_t)r * N_TOTAL + c) = v0;
            *reinterpret_cast<float2*>(out + (size_t)(r + 8) * N_TOTAL + c) = v1;
        }
    }
}

extern "C" void kernel_launch(void* const* d_in, const int* in_sizes, int n_in,
                              void* d_out, int out_size) {
    const float* data   = (const float*)d_in[0];
    const float* weight = (const float*)d_in[1];
    const float* w_mask = (const float*)d_in[2];
    const float* bias_p = (const float*)d_in[3];
    float* out = (float*)d_out;

    void* a_ptr = nullptr; void* w_ptr = nullptr;
    cudaGetSymbolAddress(&a_ptr, g_A);
    cudaGetSymbolAddress(&w_ptr, g_WB);

    {   // W*mask -> tf32 -> permute
        int nb = (N_TOTAL * K_TOTAL) / 32;
        prep_w_kernel<<<(nb + 255) / 256, 256>>>(
            (const float4*)weight, (const float4*)w_mask, (float4*)w_ptr, nb);
    }
    {   // A -> tf32 -> permute
        int nb = (M_TOTAL * K_TOTAL) / 32;
        prep_a_kernel<<<(nb + 255) / 256, 256>>>(
            (const float4*)data, (float4*)a_ptr, nb);
    }

    cudaFuncSetAttribute(gemm_tf32_kernel,
                         cudaFuncAttributeMaxDynamicSharedMemorySize, SMEM_BYTES);
    dim3 grid(N_TOTAL / BN, M_TOTAL / BM);   // (16, 64)
    gemm_tf32_kernel<<<grid, 256, SMEM_BYTES>>>(out, bias_p);
}

// round 4
// speedup vs baseline: 1.0469x; 1.0469x over previous
#include <cuda_runtime.h>
#include <cstdint>

// ---------------- problem constants ----------------
#define M_TOTAL 8192
#define N_TOTAL 4096
#define K_TOTAL 4096

// ---------------- GEMM tiling ----------------
#define BM 128
#define BN 128
#define BK 32
#define SST 36                      // smem row stride in floats (144B, 16B-aligned)
#define A_STAGE (BM * SST)          // floats
#define B_STAGE (BN * SST)
#define SMEM_BYTES (2 * (A_STAGE + B_STAGE) * 4)   // 73728 -> 2 CTAs/SM

// Scratch: TF32(RNA)-rounded, fragment-permuted copies.
// Within each 32-float k-block, value k is stored at p = (k%4)*8 + k/4.
__device__ float g_A[(size_t)M_TOTAL * K_TOTAL];   // 134 MB
__device__ float g_WB[(size_t)N_TOTAL * K_TOTAL];  // 67 MB

__device__ __forceinline__ float tf32_rna(float x) {
    unsigned u;
    asm("cvt.rna.tf32.f32 %0, %1;" : "=r"(u) : "f"(x));
    return __uint_as_float(u);
}

// ---------------- prep kernels: coalesced, smem-staged permute ----------------
// Block = 256 threads = 256 float4 = 32 k-blocks (each 8 float4).
// out[b*8+q].u = tf32(in[b*8 + 4*(q&1)+u].comp[q>>1])
__global__ __launch_bounds__(256)
void prep_a_kernel(const float4* __restrict__ in, float4* __restrict__ outp) {
    __shared__ float4 s[256];
    const int G = blockIdx.x * 256 + threadIdx.x;
    s[threadIdx.x] = in[G];
    __syncthreads();
    const float* f = reinterpret_cast<const float*>(s);
    const int q  = threadIdx.x & 7;
    const int cb = (threadIdx.x & ~7) + 4 * (q & 1);
    const int sc = q >> 1;
    float4 r;
    r.x = tf32_rna(f[(cb + 0) * 4 + sc]);
    r.y = tf32_rna(f[(cb + 1) * 4 + sc]);
    r.z = tf32_rna(f[(cb + 2) * 4 + sc]);
    r.w = tf32_rna(f[(cb + 3) * 4 + sc]);
    outp[G] = r;
}

__global__ __launch_bounds__(256)
void prep_w_kernel(const float4* __restrict__ w, const float4* __restrict__ m,
                   float4* __restrict__ outp) {
    __shared__ float4 s[256];
    const int G = blockIdx.x * 256 + threadIdx.x;
    float4 a = w[G], k = m[G], p;
    p.x = a.x * k.x; p.y = a.y * k.y; p.z = a.z * k.z; p.w = a.w * k.w;
    s[threadIdx.x] = p;
    __syncthreads();
    const float* f = reinterpret_cast<const float*>(s);
    const int q  = threadIdx.x & 7;
    const int cb = (threadIdx.x & ~7) + 4 * (q & 1);
    const int sc = q >> 1;
    float4 r;
    r.x = tf32_rna(f[(cb + 0) * 4 + sc]);
    r.y = tf32_rna(f[(cb + 1) * 4 + sc]);
    r.z = tf32_rna(f[(cb + 2) * 4 + sc]);
    r.w = tf32_rna(f[(cb + 3) * 4 + sc]);
    outp[G] = r;
}

// ---------------- GEMM ----------------
__device__ __forceinline__ void cp_async16(void* dst, const void* src) {
    unsigned sdst = (unsigned)__cvta_generic_to_shared(dst);
    asm volatile("cp.async.cg.shared.global [%0], [%1], 16;" :: "r"(sdst), "l"(src));
}

__device__ __forceinline__ void mma_tf32(float* c,
                                         unsigned a0, unsigned a1, unsigned a2, unsigned a3,
                                         unsigned b0, unsigned b1) {
    asm volatile(
        "mma.sync.aligned.m16n8k8.row.col.f32.tf32.tf32.f32 "
        "{%0,%1,%2,%3}, {%4,%5,%6,%7}, {%8,%9}, {%0,%1,%2,%3};"
        : "+f"(c[0]), "+f"(c[1]), "+f"(c[2]), "+f"(c[3])
        : "r"(a0), "r"(a1), "r"(a2), "r"(a3), "r"(b0), "r"(b1));
}

#define FU(x) __float_as_uint(x)

__global__ __launch_bounds__(128, 2)
void gemm_tf32_kernel(float* __restrict__ out, const float* __restrict__ bias) {
    extern __shared__ float smem[];
    float* As = smem;                  // [2][BM][SST]
    float* Bs = smem + 2 * A_STAGE;    // [2][BN][SST]

    const int tid  = threadIdx.x;
    const int wid  = tid >> 5;
    const int lane = tid & 31;
    const int g    = lane >> 2;        // 0..7
    const int t4   = lane & 3;         // 0..3

    const int warp_m = (wid & 1) * 64;   // 0,64
    const int warp_n = (wid >> 1) * 64;  // 0,64

    const int bm = blockIdx.y * BM;
    const int bn = blockIdx.x * BN;

    const float* Abase = g_A  + (size_t)bm * K_TOTAL;
    const float* Bbase = g_WB + (size_t)bn * K_TOTAL;

    float acc[4][8][4];
    #pragma unroll
    for (int i = 0; i < 4; i++)
        #pragma unroll
        for (int j = 0; j < 8; j++)
            #pragma unroll
            for (int r = 0; r < 4; r++) acc[i][j][r] = 0.0f;

    // Loader: A 1024 + B 1024 float4 chunks per stage; 16 per thread (128 thr).
    auto load_tile = [&](int kt, int buf) {
        const int k0 = kt * BK;
        #pragma unroll
        for (int it = 0; it < 8; it++) {          // A
            int idx = tid + it * 128;
            int row = idx >> 3, ch = idx & 7;
            cp_async16(&As[buf * A_STAGE + row * SST + ch * 4],
                       Abase + (size_t)row * K_TOTAL + k0 + ch * 4);
        }
        #pragma unroll
        for (int it = 0; it < 8; it++) {          // B
            int idx = tid + it * 128;
            int row = idx >> 3, ch = idx & 7;
            cp_async16(&Bs[buf * B_STAGE + row * SST + ch * 4],
                       Bbase + (size_t)row * K_TOTAL + k0 + ch * 4);
        }
        asm volatile("cp.async.commit_group;");
    };

    load_tile(0, 0);

    const int KT = K_TOTAL / BK;  // 128
    for (int kt = 0; kt < KT; ++kt) {
        asm volatile("cp.async.wait_group 0;");
        __syncthreads();
        const int buf = kt & 1;
        if (kt + 1 < KT) load_tile(kt + 1, buf ^ 1);

        const float* Ab = &As[buf * A_STAGE];
        const float* Bb = &Bs[buf * B_STAGE];

        #pragma unroll
        for (int ksp = 0; ksp < 2; ++ksp) {
            const int c = t4 * 8 + ksp * 4;       // permuted col, float4-aligned
            float4 aF[4][2];
            float4 bF[8];
            #pragma unroll
            for (int i = 0; i < 4; i++) {
                aF[i][0] = *reinterpret_cast<const float4*>(Ab + (warp_m + i * 16 + g) * SST + c);
                aF[i][1] = *reinterpret_cast<const float4*>(Ab + (warp_m + i * 16 + g + 8) * SST + c);
            }
            #pragma unroll
            for (int j = 0; j < 8; j++)
                bF[j] = *reinterpret_cast<const float4*>(Bb + (warp_n + j * 8 + g) * SST + c);

            #pragma unroll
            for (int i = 0; i < 4; i++) {
                #pragma unroll
                for (int j = 0; j < 8; j++) {
                    // ks = 2*ksp   : components .x (k=t4), .y (k=t4+4)
                    mma_tf32(acc[i][j],
                             FU(aF[i][0].x), FU(aF[i][1].x), FU(aF[i][0].y), FU(aF[i][1].y),
                             FU(bF[j].x), FU(bF[j].y));
                    // ks = 2*ksp+1 : components .z, .w
                    mma_tf32(acc[i][j],
                             FU(aF[i][0].z), FU(aF[i][1].z), FU(aF[i][0].w), FU(aF[i][1].w),
                             FU(bF[j].z), FU(bF[j].w));
                }
            }
        }
    }

    // Epilogue: c0,c1 @ (g, t4*2 / +1); c2,c3 @ row g+8. float2 STG, bias fused.
    const int row0 = bm + warp_m;
    const int col0 = bn + warp_n;
    #pragma unroll
    for (int j = 0; j < 8; j++) {
        int c = col0 + j * 8 + t4 * 2;
        float b0 = __ldg(bias + c), b1 = __ldg(bias + c + 1);
        #pragma unroll
        for (int i = 0; i < 4; i++) {
            int r = row0 + i * 16 + g;
            float2 v0 = make_float2(acc[i][j][0] + b0, acc[i][j][1] + b1);
            float2 v1 = make_float2(acc[i][j][2] + b0, acc[i][j][3] + b1);
            *reinterpret_cast<float2*>(out + (size_t)r * N_TOTAL + c) = v0;
            *reinterpret_cast<float2*>(out + (size_t)(r + 8) * N_TOTAL + c) = v1;
        }
    }
}

extern "C" void kernel_launch(void* const* d_in, const int* in_sizes, int n_in,
                              void* d_out, int out_size) {
    const float* data   = (const float*)d_in[0];
    const float* weight = (const float*)d_in[1];
    const float* w_mask = (const float*)d_in[2];
    const float* bias_p = (const float*)d_in[3];
    float* out = (float*)d_out;

    void* a_ptr = nullptr; void* w_ptr = nullptr;
    cudaGetSymbolAddress(&a_ptr, g_A);
    cudaGetSymbolAddress(&w_ptr, g_WB);

    {   // W*mask -> tf32 -> permute  (4096*4096/4 float4 / 256 per block)
        int blocks = (N_TOTAL * K_TOTAL) / 4 / 256;
        prep_w_kernel<<<blocks, 256>>>((const float4*)weight, (const float4*)w_mask,
                                       (float4*)w_ptr);
    }
    {   // A -> tf32 -> permute
        int blocks = (M_TOTAL * K_TOTAL) / 4 / 256;
        prep_a_kernel<<<blocks, 256>>>((const float4*)data, (float4*)a_ptr);
    }

    cudaFuncSetAttribute(gemm_tf32_kernel,
                         cudaFuncAttributeMaxDynamicSharedMemorySize, SMEM_BYTES);
    dim3 grid(N_TOTAL / BN, M_TOTAL / BM);   // (32, 64)
    gemm_tf32_kernel<<<grid, 128, SMEM_BYTES>>>(out, bias_p);
}

// round 5
// speedup vs baseline: 2.1371x; 2.0413x over previous
#include <cuda_runtime.h>
#include <cuda_fp16.h>
#include <cstdint>

// ---------------- problem constants ----------------
#define M_TOTAL 8192
#define N_TOTAL 4096
#define K_TOTAL 4096

// ---------------- GEMM tiling ----------------
#define BM 128
#define BN 128
#define BK 32                      // k per stage chunk (two k16 MMA groups)
#define STAGES 3
#define ROW_H 32                   // halfs per row per stage (64B, no pad: conflict-free)
#define A_STAGE_H (BM * ROW_H)     // 4096 halfs
#define B_STAGE_H (BN * ROW_H)
#define SMEM_BYTES (STAGES * (A_STAGE_H + B_STAGE_H) * 2)   // 49152

// Scratch: fp16, fragment-permuted. Within each 32-k block, k stored at
// pos = t*8 + gr*4 + hi*2 + lo, where t=(k%8)>>1, gr=k/16, hi=(k%16)>=8, lo=k&1.
// => thread t4's 16B (LDS.128) at offset t4*8 halfs holds exactly its
//    m16n8k16 fragment pairs for BOTH k16 groups: {x=gr0lo, y=gr0hi, z=gr1lo, w=gr1hi}.
__device__ __half g_A[(size_t)M_TOTAL * K_TOTAL];   // 67 MB
__device__ __half g_WB[(size_t)N_TOTAL * K_TOTAL];  // 33.5 MB

// ---------------- fused prep kernel ----------------
// Each 256-thread block converts 1024 consecutive floats (¼ of one K row).
// Blocks [0, NW_BLOCKS): W*mask -> fp16 permuted. Rest: A -> fp16 permuted.
#define NW_BLOCKS ((N_TOTAL * K_TOTAL) / 1024)   // 16384
#define NA_BLOCKS ((M_TOTAL * K_TOTAL) / 1024)   // 32768

__global__ __launch_bounds__(256)
void prep_kernel(const float* __restrict__ data,
                 const float* __restrict__ weight,
                 const float* __restrict__ w_mask) {
    __shared__ float f[1024];
    const int tid = threadIdx.x;
    const bool isW = blockIdx.x < NW_BLOCKS;
    const size_t base = isW ? (size_t)blockIdx.x * 1024
                            : (size_t)(blockIdx.x - NW_BLOCKS) * 1024;
    if (isW) {
        float4 v = reinterpret_cast<const float4*>(weight + base)[tid];
        float4 m = reinterpret_cast<const float4*>(w_mask + base)[tid];
        v.x *= m.x; v.y *= m.y; v.z *= m.z; v.w *= m.w;
        reinterpret_cast<float4*>(f)[tid] = v;
    } else {
        reinterpret_cast<float4*>(f)[tid] = reinterpret_cast<const float4*>(data + base)[tid];
    }
    __syncthreads();
    // thread tid emits permuted positions [tid*4, tid*4+4)
    const int bb = tid >> 3;              // 32-k block within the 1024
    const int t  = (tid & 7) >> 1;        // t4 owner
    const int gr = tid & 1;               // k16 group
    const int k0 = bb * 32 + gr * 16 + 2 * t;
    __half2 h0 = __floats2half2_rn(f[k0],     f[k0 + 1]);
    __half2 h1 = __floats2half2_rn(f[k0 + 8], f[k0 + 9]);
    __half* outp = isW ? g_WB : g_A;
    uint2 pk;
    pk.x = *reinterpret_cast<uint32_t*>(&h0);
    pk.y = *reinterpret_cast<uint32_t*>(&h1);
    reinterpret_cast<uint2*>(outp + base)[tid] = pk;
}

// ---------------- GEMM ----------------
__device__ __forceinline__ void cp_async16(void* dst, const void* src) {
    unsigned sdst = (unsigned)__cvta_generic_to_shared(dst);
    asm volatile("cp.async.cg.shared.global [%0], [%1], 16;" :: "r"(sdst), "l"(src));
}

__device__ __forceinline__ void mma_f16(float* c,
                                        unsigned a0, unsigned a1, unsigned a2, unsigned a3,
                                        unsigned b0, unsigned b1) {
    asm volatile(
        "mma.sync.aligned.m16n8k16.row.col.f32.f16.f16.f32 "
        "{%0,%1,%2,%3}, {%4,%5,%6,%7}, {%8,%9}, {%0,%1,%2,%3};"
        : "+f"(c[0]), "+f"(c[1]), "+f"(c[2]), "+f"(c[3])
        : "r"(a0), "r"(a1), "r"(a2), "r"(a3), "r"(b0), "r"(b1));
}

__global__ __launch_bounds__(128, 2)
void gemm_f16_kernel(float* __restrict__ out, const float* __restrict__ bias) {
    extern __shared__ __half smem[];
    __half* As = smem;                          // [STAGES][BM][ROW_H]
    __half* Bs = smem + STAGES * A_STAGE_H;     // [STAGES][BN][ROW_H]

    const int tid  = threadIdx.x;
    const int wid  = tid >> 5;
    const int lane = tid & 31;
    const int g    = lane >> 2;        // 0..7
    const int t4   = lane & 3;         // 0..3

    const int warp_m = (wid & 1) * 64;   // 0,64
    const int warp_n = (wid >> 1) * 64;  // 0,64

    const int bm = blockIdx.y * BM;
    const int bn = blockIdx.x * BN;

    const __half* Abase = g_A  + (size_t)bm * K_TOTAL;
    const __half* Bbase = g_WB + (size_t)bn * K_TOTAL;

    float acc[4][8][4];
    #pragma unroll
    for (int i = 0; i < 4; i++)
        #pragma unroll
        for (int j = 0; j < 8; j++)
            #pragma unroll
            for (int r = 0; r < 4; r++) acc[i][j][r] = 0.0f;

    // Stage loader: A 512 + B 512 x 16B chunks; 4+4 per thread.
    auto load_tile = [&](int kt, int buf) {
        const int k0 = kt * BK;
        #pragma unroll
        for (int it = 0; it < 4; it++) {          // A
            int idx = tid + it * 128;
            int row = idx >> 2, ch = idx & 3;
            cp_async16(&As[buf * A_STAGE_H + row * ROW_H + ch * 8],
                       Abase + (size_t)row * K_TOTAL + k0 + ch * 8);
        }
        #pragma unroll
        for (int it = 0; it < 4; it++) {          // B
            int idx = tid + it * 128;
            int row = idx >> 2, ch = idx & 3;
            cp_async16(&Bs[buf * B_STAGE_H + row * ROW_H + ch * 8],
                       Bbase + (size_t)row * K_TOTAL + k0 + ch * 8);
        }
        asm volatile("cp.async.commit_group;");
    };

    // prologue: 2 stages in flight
    load_tile(0, 0);
    load_tile(1, 1);

    const int KT = K_TOTAL / BK;  // 128
    for (int kt = 0; kt < KT; ++kt) {
        // Leave at most the newest group pending -> stage kt is complete.
        asm volatile("cp.async.wait_group 1;");
        __syncthreads();
        // Issue next tile (or an empty group to keep the wait_group logic sound).
        if (kt + 2 < KT) {
            load_tile(kt + 2, (kt + 2) % STAGES);
        } else {
            asm volatile("cp.async.commit_group;");
        }

        const int buf = kt % STAGES;
        const __half* Ab = &As[buf * A_STAGE_H];
        const __half* Bb = &Bs[buf * B_STAGE_H];

        uint4 aQ[4][2];
        uint4 bQ[8];
        #pragma unroll
        for (int i = 0; i < 4; i++) {
            aQ[i][0] = *reinterpret_cast<const uint4*>(Ab + (warp_m + i * 16 + g)     * ROW_H + t4 * 8);
            aQ[i][1] = *reinterpret_cast<const uint4*>(Ab + (warp_m + i * 16 + g + 8) * ROW_H + t4 * 8);
        }
        #pragma unroll
        for (int j = 0; j < 8; j++)
            bQ[j] = *reinterpret_cast<const uint4*>(Bb + (warp_n + j * 8 + g) * ROW_H + t4 * 8);

        #pragma unroll
        for (int i = 0; i < 4; i++) {
            #pragma unroll
            for (int j = 0; j < 8; j++) {
                // k16 group 0: {x = lo pair, y = hi pair}
                mma_f16(acc[i][j], aQ[i][0].x, aQ[i][1].x, aQ[i][0].y, aQ[i][1].y,
                        bQ[j].x, bQ[j].y);
                // k16 group 1: {z, w}
                mma_f16(acc[i][j], aQ[i][0].z, aQ[i][1].z, aQ[i][0].w, aQ[i][1].w,
                        bQ[j].z, bQ[j].w);
            }
        }
    }

    // Epilogue: c0,c1 @ (g, 2t4/2t4+1); c2,c3 @ row g+8. float2 STG, bias fused.
    const int row0 = bm + warp_m;
    const int col0 = bn + warp_n;
    #pragma unroll
    for (int j = 0; j < 8; j++) {
        int c = col0 + j * 8 + t4 * 2;
        float b0 = __ldg(bias + c), b1 = __ldg(bias + c + 1);
        #pragma unroll
        for (int i = 0; i < 4; i++) {
            int r = row0 + i * 16 + g;
            float2 v0 = make_float2(acc[i][j][0] + b0, acc[i][j][1] + b1);
            float2 v1 = make_float2(acc[i][j][2] + b0, acc[i][j][3] + b1);
            *reinterpret_cast<float2*>(out + (size_t)r * N_TOTAL + c) = v0;
            *reinterpret_cast<float2*>(out + (size_t)(r + 8) * N_TOTAL + c) = v1;
        }
    }
}

extern "C" void kernel_launch(void* const* d_in, const int* in_sizes, int n_in,
                              void* d_out, int out_size) {
    const float* data   = (const float*)d_in[0];
    const float* weight = (const float*)d_in[1];
    const float* w_mask = (const float*)d_in[2];
    const float* bias_p = (const float*)d_in[3];
    float* out = (float*)d_out;

    prep_kernel<<<NW_BLOCKS + NA_BLOCKS, 256>>>(data, weight, w_mask);

    cudaFuncSetAttribute(gemm_f16_kernel,
                         cudaFuncAttributeMaxDynamicSharedMemorySize, SMEM_BYTES);
    dim3 grid(N_TOTAL / BN, M_TOTAL / BM);   // (32, 64)
    gemm_f16_kernel<<<grid, 128, SMEM_BYTES>>>(out, bias_p);
}